// round 10
// baseline (speedup 1.0000x reference)
#include <cuda_runtime.h>
#include <math.h>

#define KLEN   4096
#define NFREQ  2049      // K/2 + 1
#define NH     1025      // folded freqs h=0..1024 (f=h pairs with f=2048-h)
#define NSIG   12
#define NBATCH 64
#define NLAG   51        // 2*25 + 1
#define NTAU   26        // tau = 0..25
#define NTP    13        // tau pairs (even, odd)
#define NPAIR  78        // 12*13/2 unique (n<=m) pairs
#define NS     9         // frequency slices (144 CTAs)
#define CH     114       // folded freqs per slice (9*114 = 1026 >= 1025)
#define CHP    115       // padded smem stride (conflict-free float4 su loads)
#define BPG    4         // batches per gcc CTA
#define GCC_BLOCK 320    // 4 batch-groups x 80 threads (78 active pairs each)
#define OUTB   (NSIG*NSIG*NLAG)   // 7344 floats per batch

// -------- device scratch (static: no allocations allowed) --------
__device__ float2 g_dft2[36 * 64];                // (c,s) of 2*pi*j*a/64, rows j=0..35
__device__ float4 g_tw1[33 * 64];                 // [d][b]: (c, s, tmr, tms) stage-1 twiddle
__device__ float4 g_lagp[NH * NTP];               // (wcE, wcO, wsE, wsO) at [h*13+tp]
__device__ float2 g_spec[NBATCH * NSIG * NFREQ];  // PHAT-normalized spectra

// -------- packed fp32x2 helpers --------
__device__ __forceinline__ unsigned long long fma_x2(unsigned long long a,
                                                     unsigned long long b,
                                                     unsigned long long c) {
    unsigned long long d;
    asm("fma.rn.f32x2 %0, %1, %2, %3;" : "=l"(d) : "l"(a), "l"(b), "l"(c));
    return d;
}
__device__ __forceinline__ unsigned long long pack2(float lo, float hi) {
    unsigned long long d;
    asm("mov.b64 %0, {%1, %2};" : "=l"(d) : "f"(lo), "f"(hi));
    return d;
}
__device__ __forceinline__ void unpack2(unsigned long long v, float& lo, float& hi) {
    asm("mov.b64 {%0, %1}, %2;" : "=f"(lo), "=f"(hi) : "l"(v));
}

// ================= init: twiddle tables =================
__global__ void init_tables_kernel() {
    int t = blockIdx.x * blockDim.x + threadIdx.x;
    int stride = gridDim.x * blockDim.x;
    for (int i = t; i < 36 * 64; i += stride) {
        int j = i >> 6, a = i & 63;
        float s, c;
        sincospif((float)(j * a) * (1.0f / 32.0f), &s, &c);   // 2*pi*j*a/64
        g_dft2[i] = make_float2(c, s);
    }
    for (int i = t; i < 33 * 64; i += stride) {
        int d = i >> 6, b = i & 63;
        float s, c, es, ec;
        sincospif((float)(b * d) * (1.0f / 2048.0f), &s, &c);   // W4096^{bd} = c - i s
        sincospif((float)b * (1.0f / 32.0f), &es, &ec);          // 2*pi*b/64
        float tmr = ec * c + es * s;     // cos(2pi b/64 - th)
        float tms = es * c - ec * s;     // sin(2pi b/64 - th)
        g_tw1[i] = make_float4(c, s, tmr, tms);
    }
    for (int i = t; i < NH * NTP; i += stride) {
        int h = i / NTP, tp = i - h * NTP;
        int tau0 = 2 * tp, tau1 = tau0 + 1;
        float s0, c0, s1, c1;
        sincospif((float)(h * tau0) * (1.0f / 2048.0f), &s0, &c0);
        sincospif((float)(h * tau1) * (1.0f / 2048.0f), &s1, &c1);
        float w = ((h == 0) ? 1.0f : 2.0f) * (1.0f / (float)KLEN);
        g_lagp[i] = make_float4(w * c0, w * c1, w * s0, w * s1);
    }
}

// ================= FFT (64x64 four-step, fully folded) + PHAT ========================
// Frozen at the round-9 form (table-based stage-1 epilogue, rsqrt PHAT).
__global__ __launch_bounds__(256) void fft_phat_kernel(const float* __restrict__ x) {
    extern __shared__ float smem[];
    float2* xf  = (float2*)smem;            // [32][64]: (xe,xo); a=0 -> (x0,x32)
    float*  Yr  = (float*)(xf + 32 * 64);   // [64 b][65] (col d), odd stride
    float*  Yi  = Yr + 64 * 65;
    float2* dft = (float2*)(Yi + 64 * 65);  // rows j=0..32 valid; padded to 36 rows

    const int t = threadIdx.x;
    const float* xin = x + (size_t)blockIdx.x * KLEN;

    for (int i = t; i < 36 * 64; i += 256) dft[i] = g_dft2[i];
    for (int i = t; i < 32 * 64; i += 256) {
        int a = i >> 6, b = i & 63;
        if (a == 0) {
            xf[b] = make_float2(xin[b], xin[32 * 64 + b]);
        } else {
            float v1 = xin[a * 64 + b];
            float v2 = xin[(64 - a) * 64 + b];
            xf[a * 64 + b] = make_float2(v1 + v2, v1 - v2);
        }
    }
    __syncthreads();

    const int bb = t & 63, q0 = t >> 6;

    // ---- stage 1: 9 packed accumulators (yr, yi) for d = q0 + 4i ----
    {
        unsigned long long acc[9];
        #pragma unroll
        for (int i = 0; i < 9; i++) acc[i] = 0ull;

        {
            float2 v = xf[64 + bb];
            unsigned long long vp = pack2(v.x, -v.y);
            #pragma unroll
            for (int i = 0; i < 9; i++) {
                int d = q0 + 4 * i;
                unsigned long long cs = *(const unsigned long long*)(dft + d * 64 + 1);
                acc[i] = fma_x2(vp, cs, acc[i]);
            }
        }
        for (int a = 2; a < 32; a += 2) {
            float2 v0 = xf[a * 64 + bb];
            float2 v1 = xf[(a + 1) * 64 + bb];
            unsigned long long vp0 = pack2(v0.x, -v0.y);
            unsigned long long vp1 = pack2(v1.x, -v1.y);
            #pragma unroll
            for (int i = 0; i < 9; i++) {
                int d = q0 + 4 * i;                    // d<=35; padded rows, junk discarded
                longlong2 w = *(const longlong2*)(dft + d * 64 + a);
                acc[i] = fma_x2(vp0, (unsigned long long)w.x, acc[i]);
                acc[i] = fma_x2(vp1, (unsigned long long)w.y, acc[i]);
            }
        }

        float2 x03 = xf[bb];           // (x0, x32)
        #pragma unroll
        for (int i = 0; i < 9; i++) {
            int d = q0 + 4 * i;
            if (d <= 32) {
                float yr, yi;
                unpack2(acc[i], yr, yi);
                yr += x03.x + ((d & 1) ? -x03.y : x03.y);
                float4 w = g_tw1[d * 64 + bb];          // (c, s, tmr, tms)
                Yr[bb * 65 + d] = yr * w.x + yi * w.y;
                Yi[bb * 65 + d] = yi * w.x - yr * w.y;
                if (d >= 1 && d <= 31) {
                    Yr[bb * 65 + (64 - d)] = yr * w.z - yi * w.w;
                    Yi[bb * 65 + (64 - d)] = -(yr * w.w + yi * w.z);
                }
            }
        }
    }
    __syncthreads();

    // ---- stage 2: d = bb, cc = q0 + 4j; b-folded, x2-unrolled with 16B twiddles ----
    {
        const int d = bb;
        float Xr[9], Xi[9];
        float z0r = Yr[d],           z0i = Yi[d];
        float z32r = Yr[32 * 65 + d], z32i = Yi[32 * 65 + d];
        #pragma unroll
        for (int j = 0; j < 9; j++) {
            int cc = q0 + 4 * j;
            float sg = (cc & 1) ? -1.f : 1.f;
            Xr[j] = z0r + sg * z32r;
            Xi[j] = z0i + sg * z32i;
        }

        {
            float z1r = Yr[65 + d],        z1i = Yi[65 + d];
            float z2r = Yr[63 * 65 + d],   z2i = Yi[63 * 65 + d];
            float zex = z1r + z2r, zey = z1i + z2i;
            float zox = z1r - z2r, zoy = z1i - z2i;
            #pragma unroll
            for (int j = 0; j < 9; j++) {
                int cc = q0 + 4 * j;
                float2 cs = dft[cc * 64 + 1];
                Xr[j] += zex * cs.x + zoy * cs.y;
                Xi[j] += zey * cs.x - zox * cs.y;
            }
        }
        for (int b = 2; b < 32; b += 2) {
            float z1r0 = Yr[b * 65 + d],          z1i0 = Yi[b * 65 + d];
            float z2r0 = Yr[(64 - b) * 65 + d],   z2i0 = Yi[(64 - b) * 65 + d];
            float z1r1 = Yr[(b + 1) * 65 + d],    z1i1 = Yi[(b + 1) * 65 + d];
            float z2r1 = Yr[(63 - b) * 65 + d],   z2i1 = Yi[(63 - b) * 65 + d];
            float zex0 = z1r0 + z2r0, zey0 = z1i0 + z2i0;
            float zox0 = z1r0 - z2r0, zoy0 = z1i0 - z2i0;
            float zex1 = z1r1 + z2r1, zey1 = z1i1 + z2i1;
            float zox1 = z1r1 - z2r1, zoy1 = z1i1 - z2i1;
            #pragma unroll
            for (int j = 0; j < 9; j++) {
                int cc = q0 + 4 * j;                   // <=35; padded rows, junk discarded
                float4 cs = *(const float4*)(dft + cc * 64 + b);
                Xr[j] += zex0 * cs.x + zoy0 * cs.y;
                Xi[j] += zey0 * cs.x - zox0 * cs.y;
                Xr[j] += zex1 * cs.z + zoy1 * cs.w;
                Xi[j] += zey1 * cs.z - zox1 * cs.w;
            }
        }

        float2* outp = g_spec + (size_t)blockIdx.x * NFREQ;
        #pragma unroll
        for (int j = 0; j < 9; j++) {
            int cc = q0 + 4 * j;
            int f = cc * 64 + d;
            if (cc <= 32 && f <= 2048) {
                float u = fmaf(Xr[j], Xr[j], fmaf(Xi[j], Xi[j], 1e-30f));
                float inv = rsqrtf(u);
                outp[f] = make_float2(Xr[j] * inv, Xi[j] * inv);
            }
        }
    }
}

// ================= GCC: folded cross-spectrum x lag twiddles =========================
// su stored as float4 (Ar,Ai,Br,Bi): 2 LDS.128 per iter (was 4 LDS.64).
// Epilogue: triangular mirror expansion + atomicAdd direct to out (reduce kernel gone).
__global__ __launch_bounds__(GCC_BLOCK, 2) void gcc_kernel(float* __restrict__ out) {
    extern __shared__ float smem[];
    float4* su = (float4*)smem;                  // [BPG][12][CHP] (Ar,Ai,Br,Bi)
    float4* T  = su + BPG * NSIG * CHP;          // [CH][13] (wcE,wcO,wsE,wsO)

    const int t = threadIdx.x;
    const int bg = blockIdx.x;
    const int f0 = blockIdx.y * CH;

    for (int i = t; i < BPG * NSIG * CH; i += GCC_BLOCK) {
        int g = i / (NSIG * CH);
        int r = i - g * (NSIG * CH);
        int sig = r / CH, hl = r - sig * CH;
        int f = f0 + hl;
        const float2* sp = g_spec + ((size_t)(bg * BPG + g) * NSIG + sig) * NFREQ;
        float2 A = (f <= 1024) ? sp[f] : make_float2(0.f, 0.f);
        float2 B = (f <= 1023) ? sp[2048 - f] : make_float2(0.f, 0.f);
        su[(g * NSIG + sig) * CHP + hl] = make_float4(A.x, A.y, B.x, B.y);
    }
    for (int i = t; i < CH * NTP; i += GCC_BLOCK) {
        int hl = i / NTP;
        int f = f0 + hl;
        T[i] = (f <= 1024) ? g_lagp[f * NTP + (i - hl * NTP)]
                           : make_float4(0.f, 0.f, 0.f, 0.f);
    }
    __syncthreads();

    const int g = t / 80, u = t - g * 80;
    if (u >= NPAIR) return;

    int n = 0, rem = u;
    #pragma unroll
    for (int k = 0; k < NSIG; k++) {
        int cnt = NSIG - k;
        if (rem < cnt) { n = k; break; }
        rem -= cnt;
    }
    const int m = n + rem;

    const float4* pn = su + g * (NSIG * CHP) + n * CHP;
    const float4* pm = su + g * (NSIG * CHP) + m * CHP;

    unsigned long long accU[NTP], accV[NTP];   // lanes = (even tau, odd tau)
    #pragma unroll
    for (int i = 0; i < NTP; i++) { accU[i] = 0ull; accV[i] = 0ull; }

    for (int hl = 0; hl < CH; hl++) {
        float4 an = pn[hl];       // (A_n.r, A_n.i, B_n.r, B_n.i)
        float4 am = pm[hl];
        float U1 = an.x * am.x + an.y * am.y;
        float V1 = an.y * am.x - an.x * am.y;
        float U2 = an.z * am.z + an.w * am.w;
        float V2 = an.w * am.z - an.z * am.w;
        unsigned long long pU = pack2(U1 + U2, U1 - U2);   // (Ue, Uo)
        unsigned long long pV = pack2(V1 - V2, V1 + V2);   // (Vme, Vpo)
        const longlong2* tw = (const longlong2*)(T + (size_t)hl * NTP);
        #pragma unroll
        for (int tp = 0; tp < NTP; tp++) {
            longlong2 w = tw[tp];   // .x = (wcE,wcO), .y = (wsE,wsO)
            accU[tp] = fma_x2((unsigned long long)w.x, pU, accU[tp]);
            accV[tp] = fma_x2((unsigned long long)w.y, pV, accV[tp]);
        }
    }

    // epilogue: mirror-expand and accumulate directly into out (9 adds per element)
    const int batch = bg * BPG + g;
    float* ob  = out + (size_t)batch * OUTB;
    float* onm = ob + (n * NSIG + m) * NLAG;
    float* omn = ob + (m * NSIG + n) * NLAG;
    #pragma unroll
    for (int tp = 0; tp < NTP; tp++) {
        float aE, aO, bE, bO;
        unpack2(accU[tp], aE, aO);
        unpack2(accV[tp], bE, bO);
        int tau0 = 2 * tp, tau1 = tau0 + 1;
        float gp0 = aE - bE, gm0 = aE + bE;
        float gp1 = aO - bO, gm1 = aO + bO;
        atomicAdd(&onm[tau0], gp0);
        atomicAdd(&onm[tau1], gp1);
        if (tau0 > 0) atomicAdd(&onm[NLAG - tau0], gm0);
        atomicAdd(&onm[NLAG - tau1], gm1);
        if (n != m) {
            atomicAdd(&omn[tau0], gm0);
            atomicAdd(&omn[tau1], gm1);
            if (tau0 > 0) atomicAdd(&omn[NLAG - tau0], gp0);
            atomicAdd(&omn[NLAG - tau1], gp1);
        }
    }
}

// ================= launch =================
extern "C" void kernel_launch(void* const* d_in, const int* in_sizes, int n_in,
                              void* d_out, int out_size) {
    const float* x = (const float*)d_in[0];
    float* out = (float*)d_out;

    const int fft_smem = 32 * 64 * (int)sizeof(float2)
                       + 2 * 64 * 65 * (int)sizeof(float)
                       + 36 * 64 * (int)sizeof(float2);     // 68,096 B
    const int gcc_smem = BPG * NSIG * CHP * (int)sizeof(float4)
                       + CH * NTP * (int)sizeof(float4);    // 88,320 + 23,712 = 112,032 B

    cudaFuncSetAttribute(fft_phat_kernel, cudaFuncAttributeMaxDynamicSharedMemorySize, fft_smem);
    cudaFuncSetAttribute(gcc_kernel,      cudaFuncAttributeMaxDynamicSharedMemorySize, gcc_smem);

    init_tables_kernel<<<128, 256>>>();
    fft_phat_kernel<<<NBATCH * NSIG, 256, fft_smem>>>(x);
    cudaMemsetAsync(d_out, 0, (size_t)out_size * sizeof(float));
    gcc_kernel<<<dim3(NBATCH / BPG, NS), GCC_BLOCK, gcc_smem>>>(out);
}

// round 11
// speedup vs baseline: 1.2725x; 1.2725x over previous
#include <cuda_runtime.h>
#include <math.h>

#define KLEN   4096
#define NFREQ  2049      // K/2 + 1
#define NH     1025      // folded freqs h=0..1024 (f=h pairs with f=2048-h)
#define NSIG   12
#define NBATCH 64
#define NLAG   51        // 2*25 + 1
#define NTAU   26        // tau = 0..25
#define NTP    13        // tau pairs (even, odd)
#define NPAIR  78        // 12*13/2 unique (n<=m) pairs
#define NS     9         // frequency slices (144 CTAs)
#define CH     114       // folded freqs per slice (9*114 = 1026 >= 1025)
#define CHP    115       // padded smem stride (conflict-free float4 su loads)
#define BPG    4         // batches per gcc CTA
#define GCC_BLOCK 320    // 4 batch-groups x 80 threads (78 active pairs each)
#define OUTB   (NSIG*NSIG*NLAG)   // 7344 floats per batch

// -------- device scratch (static: no allocations allowed) --------
__device__ float2 g_dft2[36 * 64];                // (c,s) of 2*pi*j*a/64, rows j=0..35
__device__ float4 g_tw1[33 * 64];                 // [d][b]: (c, s, tmr, tms) stage-1 twiddle
__device__ float4 g_lagp[NH * NTP];               // (wcE, wcO, wsE, wsO) at [h*13+tp]
__device__ float2 g_spec[NBATCH * NSIG * NFREQ];  // PHAT-normalized spectra
__device__ unsigned long long g_part2[NS][NBATCH][NPAIR][NTAU];  // packed (g+, g-)

// -------- packed fp32x2 helpers --------
__device__ __forceinline__ unsigned long long fma_x2(unsigned long long a,
                                                     unsigned long long b,
                                                     unsigned long long c) {
    unsigned long long d;
    asm("fma.rn.f32x2 %0, %1, %2, %3;" : "=l"(d) : "l"(a), "l"(b), "l"(c));
    return d;
}
__device__ __forceinline__ unsigned long long pack2(float lo, float hi) {
    unsigned long long d;
    asm("mov.b64 %0, {%1, %2};" : "=l"(d) : "f"(lo), "f"(hi));
    return d;
}
__device__ __forceinline__ void unpack2(unsigned long long v, float& lo, float& hi) {
    asm("mov.b64 {%0, %1}, %2;" : "=f"(lo), "=f"(hi) : "l"(v));
}

// ================= init: twiddle tables =================
__global__ void init_tables_kernel() {
    int t = blockIdx.x * blockDim.x + threadIdx.x;
    int stride = gridDim.x * blockDim.x;
    for (int i = t; i < 36 * 64; i += stride) {
        int j = i >> 6, a = i & 63;
        float s, c;
        sincospif((float)(j * a) * (1.0f / 32.0f), &s, &c);   // 2*pi*j*a/64
        g_dft2[i] = make_float2(c, s);
    }
    for (int i = t; i < 33 * 64; i += stride) {
        int d = i >> 6, b = i & 63;
        float s, c, es, ec;
        sincospif((float)(b * d) * (1.0f / 2048.0f), &s, &c);   // W4096^{bd} = c - i s
        sincospif((float)b * (1.0f / 32.0f), &es, &ec);          // 2*pi*b/64
        float tmr = ec * c + es * s;     // cos(2pi b/64 - th)
        float tms = es * c - ec * s;     // sin(2pi b/64 - th)
        g_tw1[i] = make_float4(c, s, tmr, tms);
    }
    for (int i = t; i < NH * NTP; i += stride) {
        int h = i / NTP, tp = i - h * NTP;
        int tau0 = 2 * tp, tau1 = tau0 + 1;
        float s0, c0, s1, c1;
        sincospif((float)(h * tau0) * (1.0f / 2048.0f), &s0, &c0);
        sincospif((float)(h * tau1) * (1.0f / 2048.0f), &s1, &c1);
        float w = ((h == 0) ? 1.0f : 2.0f) * (1.0f / (float)KLEN);
        g_lagp[i] = make_float4(w * c0, w * c1, w * s0, w * s1);
    }
}

// ================= FFT (64x64 four-step, fully folded) + PHAT ========================
// Round-9 form (table-based stage-1 epilogue, rsqrt PHAT) — measured best.
__global__ __launch_bounds__(256) void fft_phat_kernel(const float* __restrict__ x) {
    extern __shared__ float smem[];
    float2* xf  = (float2*)smem;            // [32][64]: (xe,xo); a=0 -> (x0,x32)
    float*  Yr  = (float*)(xf + 32 * 64);   // [64 b][65] (col d), odd stride
    float*  Yi  = Yr + 64 * 65;
    float2* dft = (float2*)(Yi + 64 * 65);  // rows j=0..32 valid; padded to 36 rows

    const int t = threadIdx.x;
    const float* xin = x + (size_t)blockIdx.x * KLEN;

    for (int i = t; i < 36 * 64; i += 256) dft[i] = g_dft2[i];
    for (int i = t; i < 32 * 64; i += 256) {
        int a = i >> 6, b = i & 63;
        if (a == 0) {
            xf[b] = make_float2(xin[b], xin[32 * 64 + b]);
        } else {
            float v1 = xin[a * 64 + b];
            float v2 = xin[(64 - a) * 64 + b];
            xf[a * 64 + b] = make_float2(v1 + v2, v1 - v2);
        }
    }
    __syncthreads();

    const int bb = t & 63, q0 = t >> 6;

    // ---- stage 1: 9 packed accumulators (yr, yi) for d = q0 + 4i ----
    {
        unsigned long long acc[9];
        #pragma unroll
        for (int i = 0; i < 9; i++) acc[i] = 0ull;

        {
            float2 v = xf[64 + bb];
            unsigned long long vp = pack2(v.x, -v.y);
            #pragma unroll
            for (int i = 0; i < 9; i++) {
                int d = q0 + 4 * i;
                unsigned long long cs = *(const unsigned long long*)(dft + d * 64 + 1);
                acc[i] = fma_x2(vp, cs, acc[i]);
            }
        }
        for (int a = 2; a < 32; a += 2) {
            float2 v0 = xf[a * 64 + bb];
            float2 v1 = xf[(a + 1) * 64 + bb];
            unsigned long long vp0 = pack2(v0.x, -v0.y);
            unsigned long long vp1 = pack2(v1.x, -v1.y);
            #pragma unroll
            for (int i = 0; i < 9; i++) {
                int d = q0 + 4 * i;                    // d<=35; padded rows, junk discarded
                longlong2 w = *(const longlong2*)(dft + d * 64 + a);
                acc[i] = fma_x2(vp0, (unsigned long long)w.x, acc[i]);
                acc[i] = fma_x2(vp1, (unsigned long long)w.y, acc[i]);
            }
        }

        float2 x03 = xf[bb];           // (x0, x32)
        #pragma unroll
        for (int i = 0; i < 9; i++) {
            int d = q0 + 4 * i;
            if (d <= 32) {
                float yr, yi;
                unpack2(acc[i], yr, yi);
                yr += x03.x + ((d & 1) ? -x03.y : x03.y);
                float4 w = g_tw1[d * 64 + bb];          // (c, s, tmr, tms)
                Yr[bb * 65 + d] = yr * w.x + yi * w.y;
                Yi[bb * 65 + d] = yi * w.x - yr * w.y;
                if (d >= 1 && d <= 31) {
                    Yr[bb * 65 + (64 - d)] = yr * w.z - yi * w.w;
                    Yi[bb * 65 + (64 - d)] = -(yr * w.w + yi * w.z);
                }
            }
        }
    }
    __syncthreads();

    // ---- stage 2: d = bb, cc = q0 + 4j; b-folded, x2-unrolled with 16B twiddles ----
    {
        const int d = bb;
        float Xr[9], Xi[9];
        float z0r = Yr[d],           z0i = Yi[d];
        float z32r = Yr[32 * 65 + d], z32i = Yi[32 * 65 + d];
        #pragma unroll
        for (int j = 0; j < 9; j++) {
            int cc = q0 + 4 * j;
            float sg = (cc & 1) ? -1.f : 1.f;
            Xr[j] = z0r + sg * z32r;
            Xi[j] = z0i + sg * z32i;
        }

        {
            float z1r = Yr[65 + d],        z1i = Yi[65 + d];
            float z2r = Yr[63 * 65 + d],   z2i = Yi[63 * 65 + d];
            float zex = z1r + z2r, zey = z1i + z2i;
            float zox = z1r - z2r, zoy = z1i - z2i;
            #pragma unroll
            for (int j = 0; j < 9; j++) {
                int cc = q0 + 4 * j;
                float2 cs = dft[cc * 64 + 1];
                Xr[j] += zex * cs.x + zoy * cs.y;
                Xi[j] += zey * cs.x - zox * cs.y;
            }
        }
        for (int b = 2; b < 32; b += 2) {
            float z1r0 = Yr[b * 65 + d],          z1i0 = Yi[b * 65 + d];
            float z2r0 = Yr[(64 - b) * 65 + d],   z2i0 = Yi[(64 - b) * 65 + d];
            float z1r1 = Yr[(b + 1) * 65 + d],    z1i1 = Yi[(b + 1) * 65 + d];
            float z2r1 = Yr[(63 - b) * 65 + d],   z2i1 = Yi[(63 - b) * 65 + d];
            float zex0 = z1r0 + z2r0, zey0 = z1i0 + z2i0;
            float zox0 = z1r0 - z2r0, zoy0 = z1i0 - z2i0;
            float zex1 = z1r1 + z2r1, zey1 = z1i1 + z2i1;
            float zox1 = z1r1 - z2r1, zoy1 = z1i1 - z2i1;
            #pragma unroll
            for (int j = 0; j < 9; j++) {
                int cc = q0 + 4 * j;                   // <=35; padded rows, junk discarded
                float4 cs = *(const float4*)(dft + cc * 64 + b);
                Xr[j] += zex0 * cs.x + zoy0 * cs.y;
                Xi[j] += zey0 * cs.x - zox0 * cs.y;
                Xr[j] += zex1 * cs.z + zoy1 * cs.w;
                Xi[j] += zey1 * cs.z - zox1 * cs.w;
            }
        }

        float2* outp = g_spec + (size_t)blockIdx.x * NFREQ;
        #pragma unroll
        for (int j = 0; j < 9; j++) {
            int cc = q0 + 4 * j;
            int f = cc * 64 + d;
            if (cc <= 32 && f <= 2048) {
                float u = fmaf(Xr[j], Xr[j], fmaf(Xi[j], Xi[j], 1e-30f));
                float inv = rsqrtf(u);
                outp[f] = make_float2(Xr[j] * inv, Xi[j] * inv);
            }
        }
    }
}

// ================= GCC: folded cross-spectrum x lag twiddles =========================
// Round-8 structure (g_part2 stores, no atomics); su merged to float4 (2 LDS.128/iter).
__global__ __launch_bounds__(GCC_BLOCK, 2) void gcc_kernel() {
    extern __shared__ float smem[];
    float4* su = (float4*)smem;                  // [BPG][12][CHP] (Ar,Ai,Br,Bi)
    float4* T  = su + BPG * NSIG * CHP;          // [CH][13] (wcE,wcO,wsE,wsO)

    const int t = threadIdx.x;
    const int bg = blockIdx.x;
    const int f0 = blockIdx.y * CH;

    for (int i = t; i < BPG * NSIG * CH; i += GCC_BLOCK) {
        int g = i / (NSIG * CH);
        int r = i - g * (NSIG * CH);
        int sig = r / CH, hl = r - sig * CH;
        int f = f0 + hl;
        const float2* sp = g_spec + ((size_t)(bg * BPG + g) * NSIG + sig) * NFREQ;
        float2 A = (f <= 1024) ? sp[f] : make_float2(0.f, 0.f);
        float2 B = (f <= 1023) ? sp[2048 - f] : make_float2(0.f, 0.f);
        su[(g * NSIG + sig) * CHP + hl] = make_float4(A.x, A.y, B.x, B.y);
    }
    for (int i = t; i < CH * NTP; i += GCC_BLOCK) {
        int hl = i / NTP;
        int f = f0 + hl;
        T[i] = (f <= 1024) ? g_lagp[f * NTP + (i - hl * NTP)]
                           : make_float4(0.f, 0.f, 0.f, 0.f);
    }
    __syncthreads();

    const int g = t / 80, u = t - g * 80;
    if (u >= NPAIR) return;

    int n = 0, rem = u;
    #pragma unroll
    for (int k = 0; k < NSIG; k++) {
        int cnt = NSIG - k;
        if (rem < cnt) { n = k; break; }
        rem -= cnt;
    }
    const int m = n + rem;

    const float4* pn = su + g * (NSIG * CHP) + n * CHP;
    const float4* pm = su + g * (NSIG * CHP) + m * CHP;

    unsigned long long accU[NTP], accV[NTP];   // lanes = (even tau, odd tau)
    #pragma unroll
    for (int i = 0; i < NTP; i++) { accU[i] = 0ull; accV[i] = 0ull; }

    for (int hl = 0; hl < CH; hl++) {
        float4 an = pn[hl];       // (A_n.r, A_n.i, B_n.r, B_n.i)
        float4 am = pm[hl];
        float U1 = an.x * am.x + an.y * am.y;
        float V1 = an.y * am.x - an.x * am.y;
        float U2 = an.z * am.z + an.w * am.w;
        float V2 = an.w * am.z - an.z * am.w;
        unsigned long long pU = pack2(U1 + U2, U1 - U2);   // (Ue, Uo)
        unsigned long long pV = pack2(V1 - V2, V1 + V2);   // (Vme, Vpo)
        const longlong2* tw = (const longlong2*)(T + (size_t)hl * NTP);
        #pragma unroll
        for (int tp = 0; tp < NTP; tp++) {
            longlong2 w = tw[tp];   // .x = (wcE,wcO), .y = (wsE,wsO)
            accU[tp] = fma_x2((unsigned long long)w.x, pU, accU[tp]);
            accV[tp] = fma_x2((unsigned long long)w.y, pV, accV[tp]);
        }
    }

    unsigned long long* pr = &g_part2[blockIdx.y][bg * BPG + g][u][0];
    #pragma unroll
    for (int tp = 0; tp < NTP; tp++) {
        float aE, aO, bE, bO;
        unpack2(accU[tp], aE, aO);
        unpack2(accV[tp], bE, bO);
        pr[2 * tp]     = pack2(aE - bE, aE + bE);   // (g+, g-) even tau
        pr[2 * tp + 1] = pack2(aO - bO, aO + bO);   // (g+, g-) odd tau
    }
}

// ================= reduce partials + triangular mirror expansion =================
// Round-8 version (measured 5.9us): thread = (batch, pair, tau-pair), 16B loads.
__global__ void reduce_kernel(float* __restrict__ out) {
    int i = blockIdx.x * blockDim.x + threadIdx.x;
    if (i >= NBATCH * NPAIR * 13) return;
    int b = i / (NPAIR * 13);
    int r = i - b * (NPAIR * 13);
    int p = r / 13, k2 = r - p * 13;
    int tau0 = 2 * k2, tau1 = tau0 + 1;

    float gp0 = 0.f, gm0 = 0.f, gp1 = 0.f, gm1 = 0.f;
    #pragma unroll
    for (int s = 0; s < NS; s++) {
        ulonglong2 v = *(const ulonglong2*)&g_part2[s][b][p][tau0];
        float lo, hi;
        unpack2(v.x, lo, hi); gp0 += lo; gm0 += hi;
        unpack2(v.y, lo, hi); gp1 += lo; gm1 += hi;
    }

    int n = 0, rem = p;
    #pragma unroll
    for (int k = 0; k < NSIG; k++) {
        int cnt = NSIG - k;
        if (rem < cnt) { n = k; break; }
        rem -= cnt;
    }
    int m = n + rem;

    float* ob  = out + (size_t)b * OUTB;
    float* onm = ob + (n * NSIG + m) * NLAG;
    onm[tau0] = gp0;
    onm[tau1] = gp1;
    if (tau0 > 0) onm[NLAG - tau0] = gm0;
    onm[NLAG - tau1] = gm1;
    if (n != m) {
        float* omn = ob + (m * NSIG + n) * NLAG;
        omn[tau0] = gm0;
        omn[tau1] = gm1;
        if (tau0 > 0) omn[NLAG - tau0] = gp0;
        omn[NLAG - tau1] = gp1;
    }
}

// ================= launch =================
extern "C" void kernel_launch(void* const* d_in, const int* in_sizes, int n_in,
                              void* d_out, int out_size) {
    const float* x = (const float*)d_in[0];
    float* out = (float*)d_out;

    const int fft_smem = 32 * 64 * (int)sizeof(float2)
                       + 2 * 64 * 65 * (int)sizeof(float)
                       + 36 * 64 * (int)sizeof(float2);     // 68,096 B
    const int gcc_smem = BPG * NSIG * CHP * (int)sizeof(float4)
                       + CH * NTP * (int)sizeof(float4);    // 112,032 B

    cudaFuncSetAttribute(fft_phat_kernel, cudaFuncAttributeMaxDynamicSharedMemorySize, fft_smem);
    cudaFuncSetAttribute(gcc_kernel,      cudaFuncAttributeMaxDynamicSharedMemorySize, gcc_smem);

    init_tables_kernel<<<128, 256>>>();
    fft_phat_kernel<<<NBATCH * NSIG, 256, fft_smem>>>(x);
    gcc_kernel<<<dim3(NBATCH / BPG, NS), GCC_BLOCK, gcc_smem>>>();
    const int rthreads = NBATCH * NPAIR * 13;
    reduce_kernel<<<(rthreads + 255) / 256, 256>>>(out);
}

// round 12
// speedup vs baseline: 1.2741x; 1.0012x over previous
#include <cuda_runtime.h>
#include <math.h>

#define KLEN   4096
#define NFREQ  2049      // K/2 + 1
#define NH     1025      // folded freqs h=0..1024 (f=h pairs with f=2048-h)
#define NSIG   12
#define NBATCH 64
#define NLAG   51        // 2*25 + 1
#define NTAU   26        // tau = 0..25
#define NTP    13        // tau pairs (even, odd)
#define NPAIR  78        // 12*13/2 unique (n<=m) pairs
#define NS     9         // frequency slices (144 CTAs)
#define CH     114       // folded freqs per slice (9*114 = 1026 >= 1025)
#define CHH    57        // half-slice per thread (2 halves combine in-CTA)
#define CHP    115       // padded smem stride (conflict-free float4 su loads)
#define BPG    4         // batches per gcc CTA
#define GCC_BLOCK 640    // 8 groups x 80 threads = 4 batches x 2 freq-halves
#define OUTB   (NSIG*NSIG*NLAG)   // 7344 floats per batch

// -------- device scratch (static: no allocations allowed) --------
__device__ float2 g_dft2[36 * 64];                // (c,s) of 2*pi*j*a/64, rows j=0..35
__device__ float4 g_tw1[33 * 64];                 // [d][b]: (c, s, tmr, tms) stage-1 twiddle
__device__ float4 g_lagp[NH * NTP];               // (wcE, wcO, wsE, wsO) at [h*13+tp]
__device__ float2 g_spec[NBATCH * NSIG * NFREQ];  // PHAT-normalized spectra
__device__ unsigned long long g_part2[NS][NBATCH][NPAIR][NTAU];  // packed (g+, g-)

// -------- packed fp32x2 helpers --------
__device__ __forceinline__ unsigned long long fma_x2(unsigned long long a,
                                                     unsigned long long b,
                                                     unsigned long long c) {
    unsigned long long d;
    asm("fma.rn.f32x2 %0, %1, %2, %3;" : "=l"(d) : "l"(a), "l"(b), "l"(c));
    return d;
}
__device__ __forceinline__ unsigned long long pack2(float lo, float hi) {
    unsigned long long d;
    asm("mov.b64 %0, {%1, %2};" : "=l"(d) : "f"(lo), "f"(hi));
    return d;
}
__device__ __forceinline__ void unpack2(unsigned long long v, float& lo, float& hi) {
    asm("mov.b64 {%0, %1}, %2;" : "=f"(lo), "=f"(hi) : "l"(v));
}

// ================= init: twiddle tables =================
__global__ void init_tables_kernel() {
    int t = blockIdx.x * blockDim.x + threadIdx.x;
    int stride = gridDim.x * blockDim.x;
    for (int i = t; i < 36 * 64; i += stride) {
        int j = i >> 6, a = i & 63;
        float s, c;
        sincospif((float)(j * a) * (1.0f / 32.0f), &s, &c);   // 2*pi*j*a/64
        g_dft2[i] = make_float2(c, s);
    }
    for (int i = t; i < 33 * 64; i += stride) {
        int d = i >> 6, b = i & 63;
        float s, c, es, ec;
        sincospif((float)(b * d) * (1.0f / 2048.0f), &s, &c);   // W4096^{bd} = c - i s
        sincospif((float)b * (1.0f / 32.0f), &es, &ec);          // 2*pi*b/64
        float tmr = ec * c + es * s;     // cos(2pi b/64 - th)
        float tms = es * c - ec * s;     // sin(2pi b/64 - th)
        g_tw1[i] = make_float4(c, s, tmr, tms);
    }
    for (int i = t; i < NH * NTP; i += stride) {
        int h = i / NTP, tp = i - h * NTP;
        int tau0 = 2 * tp, tau1 = tau0 + 1;
        float s0, c0, s1, c1;
        sincospif((float)(h * tau0) * (1.0f / 2048.0f), &s0, &c0);
        sincospif((float)(h * tau1) * (1.0f / 2048.0f), &s1, &c1);
        float w = ((h == 0) ? 1.0f : 2.0f) * (1.0f / (float)KLEN);
        g_lagp[i] = make_float4(w * c0, w * c1, w * s0, w * s1);
    }
}

// ================= FFT (64x64 four-step, fully folded) + PHAT ========================
// Frozen round-9 form (table-based stage-1 epilogue, rsqrt PHAT) — measured best.
__global__ __launch_bounds__(256) void fft_phat_kernel(const float* __restrict__ x) {
    extern __shared__ float smem[];
    float2* xf  = (float2*)smem;            // [32][64]: (xe,xo); a=0 -> (x0,x32)
    float*  Yr  = (float*)(xf + 32 * 64);   // [64 b][65] (col d), odd stride
    float*  Yi  = Yr + 64 * 65;
    float2* dft = (float2*)(Yi + 64 * 65);  // rows j=0..32 valid; padded to 36 rows

    const int t = threadIdx.x;
    const float* xin = x + (size_t)blockIdx.x * KLEN;

    for (int i = t; i < 36 * 64; i += 256) dft[i] = g_dft2[i];
    for (int i = t; i < 32 * 64; i += 256) {
        int a = i >> 6, b = i & 63;
        if (a == 0) {
            xf[b] = make_float2(xin[b], xin[32 * 64 + b]);
        } else {
            float v1 = xin[a * 64 + b];
            float v2 = xin[(64 - a) * 64 + b];
            xf[a * 64 + b] = make_float2(v1 + v2, v1 - v2);
        }
    }
    __syncthreads();

    const int bb = t & 63, q0 = t >> 6;

    // ---- stage 1: 9 packed accumulators (yr, yi) for d = q0 + 4i ----
    {
        unsigned long long acc[9];
        #pragma unroll
        for (int i = 0; i < 9; i++) acc[i] = 0ull;

        {
            float2 v = xf[64 + bb];
            unsigned long long vp = pack2(v.x, -v.y);
            #pragma unroll
            for (int i = 0; i < 9; i++) {
                int d = q0 + 4 * i;
                unsigned long long cs = *(const unsigned long long*)(dft + d * 64 + 1);
                acc[i] = fma_x2(vp, cs, acc[i]);
            }
        }
        for (int a = 2; a < 32; a += 2) {
            float2 v0 = xf[a * 64 + bb];
            float2 v1 = xf[(a + 1) * 64 + bb];
            unsigned long long vp0 = pack2(v0.x, -v0.y);
            unsigned long long vp1 = pack2(v1.x, -v1.y);
            #pragma unroll
            for (int i = 0; i < 9; i++) {
                int d = q0 + 4 * i;                    // d<=35; padded rows, junk discarded
                longlong2 w = *(const longlong2*)(dft + d * 64 + a);
                acc[i] = fma_x2(vp0, (unsigned long long)w.x, acc[i]);
                acc[i] = fma_x2(vp1, (unsigned long long)w.y, acc[i]);
            }
        }

        float2 x03 = xf[bb];           // (x0, x32)
        #pragma unroll
        for (int i = 0; i < 9; i++) {
            int d = q0 + 4 * i;
            if (d <= 32) {
                float yr, yi;
                unpack2(acc[i], yr, yi);
                yr += x03.x + ((d & 1) ? -x03.y : x03.y);
                float4 w = g_tw1[d * 64 + bb];          // (c, s, tmr, tms)
                Yr[bb * 65 + d] = yr * w.x + yi * w.y;
                Yi[bb * 65 + d] = yi * w.x - yr * w.y;
                if (d >= 1 && d <= 31) {
                    Yr[bb * 65 + (64 - d)] = yr * w.z - yi * w.w;
                    Yi[bb * 65 + (64 - d)] = -(yr * w.w + yi * w.z);
                }
            }
        }
    }
    __syncthreads();

    // ---- stage 2: d = bb, cc = q0 + 4j; b-folded, x2-unrolled with 16B twiddles ----
    {
        const int d = bb;
        float Xr[9], Xi[9];
        float z0r = Yr[d],           z0i = Yi[d];
        float z32r = Yr[32 * 65 + d], z32i = Yi[32 * 65 + d];
        #pragma unroll
        for (int j = 0; j < 9; j++) {
            int cc = q0 + 4 * j;
            float sg = (cc & 1) ? -1.f : 1.f;
            Xr[j] = z0r + sg * z32r;
            Xi[j] = z0i + sg * z32i;
        }

        {
            float z1r = Yr[65 + d],        z1i = Yi[65 + d];
            float z2r = Yr[63 * 65 + d],   z2i = Yi[63 * 65 + d];
            float zex = z1r + z2r, zey = z1i + z2i;
            float zox = z1r - z2r, zoy = z1i - z2i;
            #pragma unroll
            for (int j = 0; j < 9; j++) {
                int cc = q0 + 4 * j;
                float2 cs = dft[cc * 64 + 1];
                Xr[j] += zex * cs.x + zoy * cs.y;
                Xi[j] += zey * cs.x - zox * cs.y;
            }
        }
        for (int b = 2; b < 32; b += 2) {
            float z1r0 = Yr[b * 65 + d],          z1i0 = Yi[b * 65 + d];
            float z2r0 = Yr[(64 - b) * 65 + d],   z2i0 = Yi[(64 - b) * 65 + d];
            float z1r1 = Yr[(b + 1) * 65 + d],    z1i1 = Yi[(b + 1) * 65 + d];
            float z2r1 = Yr[(63 - b) * 65 + d],   z2i1 = Yi[(63 - b) * 65 + d];
            float zex0 = z1r0 + z2r0, zey0 = z1i0 + z2i0;
            float zox0 = z1r0 - z2r0, zoy0 = z1i0 - z2i0;
            float zex1 = z1r1 + z2r1, zey1 = z1i1 + z2i1;
            float zox1 = z1r1 - z2r1, zoy1 = z1i1 - z2i1;
            #pragma unroll
            for (int j = 0; j < 9; j++) {
                int cc = q0 + 4 * j;                   // <=35; padded rows, junk discarded
                float4 cs = *(const float4*)(dft + cc * 64 + b);
                Xr[j] += zex0 * cs.x + zoy0 * cs.y;
                Xi[j] += zey0 * cs.x - zox0 * cs.y;
                Xr[j] += zex1 * cs.z + zoy1 * cs.w;
                Xi[j] += zey1 * cs.z - zox1 * cs.w;
            }
        }

        float2* outp = g_spec + (size_t)blockIdx.x * NFREQ;
        #pragma unroll
        for (int j = 0; j < 9; j++) {
            int cc = q0 + 4 * j;
            int f = cc * 64 + d;
            if (cc <= 32 && f <= 2048) {
                float u = fmaf(Xr[j], Xr[j], fmaf(Xi[j], Xi[j], 1e-30f));
                float inv = rsqrtf(u);
                outp[f] = make_float2(Xr[j] * inv, Xi[j] * inv);
            }
        }
    }
}

// ================= GCC: folded cross-spectrum x lag twiddles =========================
// 640 threads = 8 groups (4 batches x 2 freq-halves): each (batch,pair) split across
// 2 threads (hl [0,57) / [57,114)) -> 20 warps/SM (2x latency hiding). Halves combine
// in-CTA via smem staging (unions with dead su region); g_part2 / reduce unchanged.
__global__ __launch_bounds__(GCC_BLOCK, 1) void gcc_kernel() {
    extern __shared__ float smem[];
    float4* su = (float4*)smem;                  // [BPG][12][CHP] (Ar,Ai,Br,Bi)
    float4* T  = su + BPG * NSIG * CHP;          // [CH][13] (wcE,wcO,wsE,wsO)
    unsigned long long* stage = (unsigned long long*)su;  // reused after mainloop

    const int t = threadIdx.x;
    const int bg = blockIdx.x;
    const int f0 = blockIdx.y * CH;

    for (int i = t; i < BPG * NSIG * CH; i += GCC_BLOCK) {
        int g = i / (NSIG * CH);
        int r = i - g * (NSIG * CH);
        int sig = r / CH, hl = r - sig * CH;
        int f = f0 + hl;
        const float2* sp = g_spec + ((size_t)(bg * BPG + g) * NSIG + sig) * NFREQ;
        float2 A = (f <= 1024) ? sp[f] : make_float2(0.f, 0.f);
        float2 B = (f <= 1023) ? sp[2048 - f] : make_float2(0.f, 0.f);
        su[(g * NSIG + sig) * CHP + hl] = make_float4(A.x, A.y, B.x, B.y);
    }
    for (int i = t; i < CH * NTP; i += GCC_BLOCK) {
        int hl = i / NTP;
        int f = f0 + hl;
        T[i] = (f <= 1024) ? g_lagp[f * NTP + (i - hl * NTP)]
                           : make_float4(0.f, 0.f, 0.f, 0.f);
    }
    __syncthreads();

    const int grp = t / 80, u = t - grp * 80;
    const int gb = grp >> 1;          // batch within CTA (0..3)
    const int half = grp & 1;         // frequency half
    const bool active = (u < NPAIR);

    unsigned long long accU[NTP], accV[NTP];   // lanes = (even tau, odd tau)
    #pragma unroll
    for (int i = 0; i < NTP; i++) { accU[i] = 0ull; accV[i] = 0ull; }

    if (active) {
        int n = 0, rem = u;
        #pragma unroll
        for (int k = 0; k < NSIG; k++) {
            int cnt = NSIG - k;
            if (rem < cnt) { n = k; break; }
            rem -= cnt;
        }
        const int m = n + rem;

        const float4* pn = su + gb * (NSIG * CHP) + n * CHP;
        const float4* pm = su + gb * (NSIG * CHP) + m * CHP;

        const int h0 = half * CHH;
        for (int hl = h0; hl < h0 + CHH; hl++) {
            float4 an = pn[hl];
            float4 am = pm[hl];
            float U1 = an.x * am.x + an.y * am.y;
            float V1 = an.y * am.x - an.x * am.y;
            float U2 = an.z * am.z + an.w * am.w;
            float V2 = an.w * am.z - an.z * am.w;
            unsigned long long pU = pack2(U1 + U2, U1 - U2);   // (Ue, Uo)
            unsigned long long pV = pack2(V1 - V2, V1 + V2);   // (Vme, Vpo)
            const longlong2* tw = (const longlong2*)(T + (size_t)hl * NTP);
            #pragma unroll
            for (int tp = 0; tp < NTP; tp++) {
                longlong2 w = tw[tp];   // .x = (wcE,wcO), .y = (wsE,wsO)
                accU[tp] = fma_x2((unsigned long long)w.x, pU, accU[tp]);
                accV[tp] = fma_x2((unsigned long long)w.y, pV, accV[tp]);
            }
        }
    }
    __syncthreads();   // su reads complete; staging region now safe to overwrite

    // half=1 threads stage their accumulators
    if (active && half == 1) {
        unsigned long long* st = stage + ((size_t)gb * NPAIR + u) * 26;
        #pragma unroll
        for (int tp = 0; tp < NTP; tp++) { st[tp] = accU[tp]; st[NTP + tp] = accV[tp]; }
    }
    __syncthreads();

    // half=0 threads combine and write partials (g_part2 layout unchanged, NS=9)
    if (active && half == 0) {
        const unsigned long long* st = stage + ((size_t)gb * NPAIR + u) * 26;
        const unsigned long long ONE2 = pack2(1.0f, 1.0f);
        #pragma unroll
        for (int tp = 0; tp < NTP; tp++) {
            accU[tp] = fma_x2(ONE2, st[tp], accU[tp]);
            accV[tp] = fma_x2(ONE2, st[NTP + tp], accV[tp]);
        }
        unsigned long long* pr = &g_part2[blockIdx.y][bg * BPG + gb][u][0];
        #pragma unroll
        for (int tp = 0; tp < NTP; tp++) {
            float aE, aO, bE, bO;
            unpack2(accU[tp], aE, aO);
            unpack2(accV[tp], bE, bO);
            pr[2 * tp]     = pack2(aE - bE, aE + bE);   // (g+, g-) even tau
            pr[2 * tp + 1] = pack2(aO - bO, aO + bO);   // (g+, g-) odd tau
        }
    }
}

// ================= reduce partials + triangular mirror expansion =================
// Frozen round-8 version (measured ~6us): thread = (batch, pair, tau-pair).
__global__ void reduce_kernel(float* __restrict__ out) {
    int i = blockIdx.x * blockDim.x + threadIdx.x;
    if (i >= NBATCH * NPAIR * 13) return;
    int b = i / (NPAIR * 13);
    int r = i - b * (NPAIR * 13);
    int p = r / 13, k2 = r - p * 13;
    int tau0 = 2 * k2, tau1 = tau0 + 1;

    float gp0 = 0.f, gm0 = 0.f, gp1 = 0.f, gm1 = 0.f;
    #pragma unroll
    for (int s = 0; s < NS; s++) {
        ulonglong2 v = *(const ulonglong2*)&g_part2[s][b][p][tau0];
        float lo, hi;
        unpack2(v.x, lo, hi); gp0 += lo; gm0 += hi;
        unpack2(v.y, lo, hi); gp1 += lo; gm1 += hi;
    }

    int n = 0, rem = p;
    #pragma unroll
    for (int k = 0; k < NSIG; k++) {
        int cnt = NSIG - k;
        if (rem < cnt) { n = k; break; }
        rem -= cnt;
    }
    int m = n + rem;

    float* ob  = out + (size_t)b * OUTB;
    float* onm = ob + (n * NSIG + m) * NLAG;
    onm[tau0] = gp0;
    onm[tau1] = gp1;
    if (tau0 > 0) onm[NLAG - tau0] = gm0;
    onm[NLAG - tau1] = gm1;
    if (n != m) {
        float* omn = ob + (m * NSIG + n) * NLAG;
        omn[tau0] = gm0;
        omn[tau1] = gm1;
        if (tau0 > 0) omn[NLAG - tau0] = gp0;
        omn[NLAG - tau1] = gp1;
    }
}

// ================= launch =================
extern "C" void kernel_launch(void* const* d_in, const int* in_sizes, int n_in,
                              void* d_out, int out_size) {
    const float* x = (const float*)d_in[0];
    float* out = (float*)d_out;

    const int fft_smem = 32 * 64 * (int)sizeof(float2)
                       + 2 * 64 * 65 * (int)sizeof(float)
                       + 36 * 64 * (int)sizeof(float2);     // 68,096 B
    const int gcc_smem = BPG * NSIG * CHP * (int)sizeof(float4)
                       + CH * NTP * (int)sizeof(float4);    // 112,032 B

    cudaFuncSetAttribute(fft_phat_kernel, cudaFuncAttributeMaxDynamicSharedMemorySize, fft_smem);
    cudaFuncSetAttribute(gcc_kernel,      cudaFuncAttributeMaxDynamicSharedMemorySize, gcc_smem);

    init_tables_kernel<<<128, 256>>>();
    fft_phat_kernel<<<NBATCH * NSIG, 256, fft_smem>>>(x);
    gcc_kernel<<<dim3(NBATCH / BPG, NS), GCC_BLOCK, gcc_smem>>>();
    const int rthreads = NBATCH * NPAIR * 13;
    reduce_kernel<<<(rthreads + 255) / 256, 256>>>(out);
}